// round 15
// baseline (speedup 1.0000x reference)
#include <cuda_runtime.h>
#include <cstdint>
#include <cstddef>

#define D_MODEL 1024
#define NHEAD   16
#define HEAD_DIM 64
#define BATCH   4
#define SEQ     2048
#define MTOT    (BATCH * SEQ)   // 8192

// Scratch (device globals: allocation-free)
__device__ float g_Q[MTOT * D_MODEL];
__device__ float g_K[MTOT * D_MODEL];
__device__ float g_V[MTOT * D_MODEL];
__device__ float g_O[MTOT * D_MODEL];
__device__ float g_WT[4][D_MODEL * D_MODEL];     // transposed weights [N,K]
// Fragment-major split-bf16 K/V: [bh][kt][frag(32)][lane(32)] uint4
__device__ uint4 g_Kf[64 * 32 * 32 * 32];
__device__ uint4 g_Vf[64 * 32 * 32 * 32];

// ---------------------------------------------------------------------------
// bf16 helpers
// ---------------------------------------------------------------------------
__device__ __forceinline__ uint32_t pack_bf16x2(float y, float x) {
    uint32_t r;
    asm("cvt.rn.bf16x2.f32 %0, %1, %2;" : "=r"(r) : "f"(y), "f"(x));
    return r;
}

__device__ __forceinline__ void mma_bf16(float* d, const uint32_t* a,
                                         const uint32_t* b) {
    asm volatile(
        "mma.sync.aligned.m16n8k16.row.col.f32.bf16.bf16.f32 "
        "{%0,%1,%2,%3}, {%4,%5,%6,%7}, {%8,%9}, {%0,%1,%2,%3};\n"
        : "+f"(d[0]), "+f"(d[1]), "+f"(d[2]), "+f"(d[3])
        : "r"(a[0]), "r"(a[1]), "r"(a[2]), "r"(a[3]),
          "r"(b[0]), "r"(b[1]));
}

// Split a float4 into hi-pair and lo-pair bf16x2 words.
__device__ __forceinline__ void split4(float4 v, uint32_t& h01, uint32_t& l01,
                                       uint32_t& h23, uint32_t& l23) {
    h01 = pack_bf16x2(v.y, v.x);
    h23 = pack_bf16x2(v.w, v.z);
    const float hx = __uint_as_float(h01 << 16);
    const float hy = __uint_as_float(h01 & 0xFFFF0000u);
    const float hz = __uint_as_float(h23 << 16);
    const float hw = __uint_as_float(h23 & 0xFFFF0000u);
    l01 = pack_bf16x2(v.y - hy, v.x - hx);
    l23 = pack_bf16x2(v.w - hw, v.z - hz);
}

// Split two floats (p0 -> lo half, p1 -> hi half) into hi/lo bf16x2 words.
__device__ __forceinline__ void split2(float p0, float p1,
                                       uint32_t& hi, uint32_t& lo) {
    hi = pack_bf16x2(p1, p0);
    const float h0 = __uint_as_float(hi << 16);
    const float h1 = __uint_as_float(hi & 0xFFFF0000u);
    lo = pack_bf16x2(p1 - h1, p0 - h0);
}

// ---------------------------------------------------------------------------
// 1024x1024 transpose: WT[n,k] = W[k,n]
// ---------------------------------------------------------------------------
__global__ void __launch_bounds__(256) transpose_w(
    const float* __restrict__ W, float* __restrict__ WT)
{
    __shared__ float tile[32][33];
    const int bx = blockIdx.x * 32, by = blockIdx.y * 32;
    const int tx = threadIdx.x, ty = threadIdx.y;
    #pragma unroll
    for (int i = 0; i < 32; i += 8)
        tile[ty + i][tx] = W[(size_t)(by + ty + i) * D_MODEL + bx + tx];
    __syncthreads();
    #pragma unroll
    for (int i = 0; i < 32; i += 8)
        WT[(size_t)(bx + ty + i) * D_MODEL + by + tx] = tile[tx][ty + i];
}

// ---------------------------------------------------------------------------
// Pre-pass: build K fragments. Grid (32 kt, 64 bh), block 1024.
// Fragment (ks,nt), lane (r,c): word0 = K[key 8nt+r][dims 16ks+2c..+1] hi,
// word1 = dims +8 hi; words 2,3 = lo. (Layout validated in R12.)
// ---------------------------------------------------------------------------
__global__ void __launch_bounds__(1024) build_kf(
    const float* __restrict__ gK, uint4* __restrict__ Kf)
{
    const int kt = blockIdx.x, bh = blockIdx.y;
    const int b = bh >> 4, h = bh & 15;
    const int fi = threadIdx.x >> 5;     // ks*8 + nt
    const int lane = threadIdx.x & 31;
    const int ks = fi >> 3, nt = fi & 7;
    const int r = lane >> 2, c = lane & 3;

    const float* row = gK + ((size_t)(b * SEQ + kt * 64 + nt * 8 + r)) * D_MODEL
                          + h * HEAD_DIM + 16 * ks;
    const float2 a = *(const float2*)(row + 2 * c);
    const float2 d = *(const float2*)(row + 2 * c + 8);
    uint32_t h0, l0, h1, l1;
    split2(a.x, a.y, h0, l0);
    split2(d.x, d.y, h1, l1);
    Kf[((size_t)(bh * 32 + kt) * 32 + fi) * 32 + lane] = make_uint4(h0, h1, l0, l1);
}

// ---------------------------------------------------------------------------
// Pre-pass: build V fragments (transposed). Fragment (pk,nt), lane (r,c):
// word0 = V[keys 2(8pk+c), +1][dim 8nt+r] hi; word1 = keys 2(8pk+c+4) pair hi;
// words 2,3 = lo.
// ---------------------------------------------------------------------------
__global__ void __launch_bounds__(1024) build_vf(
    const float* __restrict__ gV, uint4* __restrict__ Vf)
{
    const int kt = blockIdx.x, bh = blockIdx.y;
    const int b = bh >> 4, h = bh & 15;
    const int fi = threadIdx.x >> 5;     // pk*8 + nt
    const int lane = threadIdx.x & 31;
    const int pk = fi >> 3, nt = fi & 7;
    const int r = lane >> 2, c = lane & 3;
    const int d = nt * 8 + r;

    const int kA = kt * 64 + 2 * (8 * pk + c);
    const int kB = kt * 64 + 2 * (8 * pk + c + 4);
    const float* base = gV + (size_t)(b * SEQ) * D_MODEL + h * HEAD_DIM + d;
    const float vA0 = base[(size_t)kA * D_MODEL];
    const float vA1 = base[(size_t)(kA + 1) * D_MODEL];
    const float vB0 = base[(size_t)kB * D_MODEL];
    const float vB1 = base[(size_t)(kB + 1) * D_MODEL];
    uint32_t h0, l0, h1, l1;
    split2(vA0, vA1, h0, l0);
    split2(vB0, vB1, h1, l1);
    Vf[((size_t)(bh * 32 + kt) * 32 + fi) * 32 + lane] = make_uint4(h0, h1, l0, l1);
}

// ---------------------------------------------------------------------------
// Tensor-core GEMM, bf16 split mma + register-staged gmem prefetch.
// (Unchanged — measured at its mma floor, ~120us per GEMM.)
// ---------------------------------------------------------------------------
#define GW 36

__global__ void __launch_bounds__(256) gemm_bf16_mma(
    const float* __restrict__ A, const float* __restrict__ WT,
    const float* __restrict__ bias, float* __restrict__ C,
    int M, int N, int K)
{
    __shared__ uint32_t As[128][GW];
    __shared__ uint32_t Bs[128][GW];

    const int tid  = threadIdx.x;
    const int wid  = tid >> 5;
    const int lane = tid & 31;
    const int wm   = wid & 1;
    const int wn   = wid >> 1;
    const int bm   = blockIdx.y * 128;
    const int bn   = blockIdx.x * 128;

    const int r = lane >> 2;
    const int c = lane & 3;

    float acc[4][4][4];
    #pragma unroll
    for (int mt = 0; mt < 4; mt++)
        #pragma unroll
        for (int nt = 0; nt < 4; nt++)
            #pragma unroll
            for (int i = 0; i < 4; i++) acc[mt][nt][i] = 0.0f;

    const int lrow = tid >> 1;
    const int lcol = (tid & 1) * 16;
    const float* Arow = A  + (size_t)(bm + lrow) * K + lcol;
    const float* Brow = WT + (size_t)(bn + lrow) * K + lcol;

    float4 ra[4], rb[4];
    #pragma unroll
    for (int j = 0; j < 4; j++) {
        ra[j] = *(const float4*)(Arow + 4 * j);
        rb[j] = *(const float4*)(Brow + 4 * j);
    }

    for (int kt = 0; kt < K; kt += 32) {
        #pragma unroll
        for (int j = 0; j < 4; j++) {
            const int w = (lcol >> 1) + 2 * j;
            uint32_t h01, l01, h23, l23;
            split4(ra[j], h01, l01, h23, l23);
            *(uint2*)&As[lrow][w]      = make_uint2(h01, h23);
            *(uint2*)&As[lrow][16 + w] = make_uint2(l01, l23);
            split4(rb[j], h01, l01, h23, l23);
            *(uint2*)&Bs[lrow][w]      = make_uint2(h01, h23);
            *(uint2*)&Bs[lrow][16 + w] = make_uint2(l01, l23);
        }
        __syncthreads();

        if (kt + 32 < K) {
            #pragma unroll
            for (int j = 0; j < 4; j++) {
                ra[j] = *(const float4*)(Arow + kt + 32 + 4 * j);
                rb[j] = *(const float4*)(Brow + kt + 32 + 4 * j);
            }
        }

        #pragma unroll
        for (int ks = 0; ks < 2; ks++) {
            const int kw = ks * 8;

            uint32_t ahi[4][4], alo[4][4];
            #pragma unroll
            for (int mt = 0; mt < 4; mt++) {
                const int m0 = 64 * wm + 16 * mt;
                ahi[mt][0] = As[m0 + r][kw + c];
                ahi[mt][1] = As[m0 + r + 8][kw + c];
                ahi[mt][2] = As[m0 + r][kw + c + 4];
                ahi[mt][3] = As[m0 + r + 8][kw + c + 4];
                alo[mt][0] = As[m0 + r][16 + kw + c];
                alo[mt][1] = As[m0 + r + 8][16 + kw + c];
                alo[mt][2] = As[m0 + r][16 + kw + c + 4];
                alo[mt][3] = As[m0 + r + 8][16 + kw + c + 4];
            }

            uint32_t bhi[4][2], blo[4][2];
            #pragma unroll
            for (int nt = 0; nt < 4; nt++) {
                const int n0 = 32 * wn + 8 * nt;
                bhi[nt][0] = Bs[n0 + r][kw + c];
                bhi[nt][1] = Bs[n0 + r][kw + c + 4];
                blo[nt][0] = Bs[n0 + r][16 + kw + c];
                blo[nt][1] = Bs[n0 + r][16 + kw + c + 4];
            }

            #pragma unroll
            for (int mt = 0; mt < 4; mt++)
                #pragma unroll
                for (int nt = 0; nt < 4; nt++) {
                    mma_bf16(acc[mt][nt], ahi[mt], bhi[nt]);
                    mma_bf16(acc[mt][nt], ahi[mt], blo[nt]);
                    mma_bf16(acc[mt][nt], alo[mt], bhi[nt]);
                }
        }
        __syncthreads();
    }

    #pragma unroll
    for (int mt = 0; mt < 4; mt++) {
        const int row = bm + 64 * wm + 16 * mt + r;
        #pragma unroll
        for (int nt = 0; nt < 4; nt++) {
            const int col = bn + 32 * wn + 8 * nt + 2 * c;
            const float b0 = bias[col], b1 = bias[col + 1];
            float2 v0 = make_float2(acc[mt][nt][0] + b0, acc[mt][nt][1] + b1);
            float2 v1 = make_float2(acc[mt][nt][2] + b0, acc[mt][nt][3] + b1);
            *(float2*)(C + (size_t)row * N + col) = v0;
            *(float2*)(C + (size_t)(row + 8) * N + col) = v1;
        }
    }
}

// ---------------------------------------------------------------------------
// Tensor-core flash attention, gmem fragment K/V (no K/V smem, no barriers
// in the key loop). 128 queries per block (8 warps). Grid (SEQ/128, B*H).
// Max-free softmax, deferred sum reduction (R14).
// ---------------------------------------------------------------------------
#define AS_STRIDE 68
#define ATTN_SMEM_BYTES (128 * AS_STRIDE * 4)

__global__ void __launch_bounds__(256) attn_mma_kernel(
    const float* __restrict__ gQ, const uint4* __restrict__ Kf,
    const uint4* __restrict__ Vf, float* __restrict__ gO)
{
    extern __shared__ uint32_t smw[];
    uint32_t* Qs = smw;                       // 128 x 68

    const int t    = threadIdx.x;
    const int wid  = t >> 5;
    const int lane = t & 31;
    const int r    = lane >> 2;     // 0..7
    const int c    = lane & 3;      // 0..3
    const int bh   = blockIdx.y;
    const int b    = bh >> 4;
    const int h    = bh & 15;
    const int qt   = blockIdx.x;

    // ---- Fill Q (scaled by 1/8), split bf16: 128 rows ----
    {
        const int row   = t >> 1;            // 0..127
        const int dbase = (t & 1) * 32;
        const float* src = gQ + ((size_t)(b * SEQ + qt * 128 + row)) * D_MODEL
                               + h * HEAD_DIM + dbase;
        #pragma unroll
        for (int j = 0; j < 8; j++) {
            float4 v = *(const float4*)(src + 4 * j);
            v.x *= 0.125f; v.y *= 0.125f; v.z *= 0.125f; v.w *= 0.125f;
            uint32_t h01, l01, h23, l23;
            split4(v, h01, l01, h23, l23);
            const int w = (dbase >> 1) + 2 * j;
            Qs[row * AS_STRIDE + w]          = h01;
            Qs[row * AS_STRIDE + w + 1]      = h23;
            Qs[row * AS_STRIDE + 32 + w]     = l01;
            Qs[row * AS_STRIDE + 32 + w + 1] = l23;
        }
    }
    __syncthreads();

    // ---- Hoist Q fragments (per warp: rows 16*wid..+15) ----
    const int m0 = 16 * wid;
    uint32_t qhi[4][4], qlo[4][4];
    #pragma unroll
    for (int ks = 0; ks < 4; ks++) {
        const int kw = ks * 8;
        qhi[ks][0] = Qs[(m0 + r) * AS_STRIDE + kw + c];
        qhi[ks][1] = Qs[(m0 + r + 8) * AS_STRIDE + kw + c];
        qhi[ks][2] = Qs[(m0 + r) * AS_STRIDE + kw + c + 4];
        qhi[ks][3] = Qs[(m0 + r + 8) * AS_STRIDE + kw + c + 4];
        qlo[ks][0] = Qs[(m0 + r) * AS_STRIDE + 32 + kw + c];
        qlo[ks][1] = Qs[(m0 + r + 8) * AS_STRIDE + 32 + kw + c];
        qlo[ks][2] = Qs[(m0 + r) * AS_STRIDE + 32 + kw + c + 4];
        qlo[ks][3] = Qs[(m0 + r + 8) * AS_STRIDE + 32 + kw + c + 4];
    }

    float accO[8][4];
    #pragma unroll
    for (int nt = 0; nt < 8; nt++)
        #pragma unroll
        for (int i = 0; i < 4; i++) accO[nt][i] = 0.0f;
    float lr0 = 0.0f, lr1 = 0.0f;   // per-thread partial sums of exp(s)

    const uint4* KfB = Kf + (size_t)bh * 32 * 32 * 32 + lane;
    const uint4* VfB = Vf + (size_t)bh * 32 * 32 * 32 + lane;

    for (int kt = 0; kt < SEQ / 64; kt++) {
        const uint4* kf = KfB + (size_t)kt * 32 * 32;
        const uint4* vf = VfB + (size_t)kt * 32 * 32;

        // ---- Scores S = Q K^T (16 x 64 per warp) ----
        float acc[8][4];
        #pragma unroll
        for (int nt = 0; nt < 8; nt++)
            #pragma unroll
            for (int i = 0; i < 4; i++) acc[nt][i] = 0.0f;

        #pragma unroll
        for (int ks = 0; ks < 4; ks++) {
            #pragma unroll
            for (int nt = 0; nt < 8; nt++) {
                const uint4 kb = kf[(ks * 8 + nt) * 32];
                const uint32_t bhi[2] = {kb.x, kb.y};
                const uint32_t blo[2] = {kb.z, kb.w};
                mma_bf16(acc[nt], qhi[ks], bhi);
                mma_bf16(acc[nt], qhi[ks], blo);
                mma_bf16(acc[nt], qlo[ks], bhi);
            }
        }

        // ---- Max-free softmax: P = exp(S); accumulate local sums ----
        #pragma unroll
        for (int nt = 0; nt < 8; nt++) {
            acc[nt][0] = __expf(acc[nt][0]);
            acc[nt][1] = __expf(acc[nt][1]);
            acc[nt][2] = __expf(acc[nt][2]);
            acc[nt][3] = __expf(acc[nt][3]);
            lr0 += acc[nt][0] + acc[nt][1];
            lr1 += acc[nt][2] + acc[nt][3];
        }

        // ---- O += P V : P fragments straight from score regs ----
        #pragma unroll
        for (int pk = 0; pk < 4; pk++) {
            uint32_t phi[4], plo[4];
            split2(acc[2 * pk][0],     acc[2 * pk][1],     phi[0], plo[0]);
            split2(acc[2 * pk][2],     acc[2 * pk][3],     phi[1], plo[1]);
            split2(acc[2 * pk + 1][0], acc[2 * pk + 1][1], phi[2], plo[2]);
            split2(acc[2 * pk + 1][2], acc[2 * pk + 1][3], phi[3], plo[3]);
            #pragma unroll
            for (int nt = 0; nt < 8; nt++) {
                const uint4 vb = vf[(pk * 8 + nt) * 32];
                const uint32_t vhi[2] = {vb.x, vb.y};
                const uint32_t vlo[2] = {vb.z, vb.w};
                mma_bf16(accO[nt], phi, vhi);
                mma_bf16(accO[nt], phi, vlo);
                mma_bf16(accO[nt], plo, vhi);
            }
        }
    }

    // ---- Deferred sum reduction (once) + epilogue ----
    lr0 += __shfl_xor_sync(0xffffffffu, lr0, 1);
    lr0 += __shfl_xor_sync(0xffffffffu, lr0, 2);
    lr1 += __shfl_xor_sync(0xffffffffu, lr1, 1);
    lr1 += __shfl_xor_sync(0xffffffffu, lr1, 2);
    const float rc0 = 1.0f / lr0;
    const float rc1 = 1.0f / lr1;
    const size_t row0 = (size_t)(b * SEQ + qt * 128 + m0 + r) * D_MODEL
                        + h * HEAD_DIM;
    const size_t row1 = row0 + 8 * D_MODEL;
    #pragma unroll
    for (int nt = 0; nt < 8; nt++) {
        const int col = 8 * nt + 2 * c;
        *(float2*)(gO + row0 + col) =
            make_float2(accO[nt][0] * rc0, accO[nt][1] * rc0);
        *(float2*)(gO + row1 + col) =
            make_float2(accO[nt][2] * rc1, accO[nt][3] * rc1);
    }
}

// ---------------------------------------------------------------------------
extern "C" void kernel_launch(void* const* d_in, const int* in_sizes, int n_in,
                              void* d_out, int out_size)
{
    const float* x  = (const float*)d_in[0];
    const float* y  = (const float*)d_in[1];
    const float* wq = (const float*)d_in[2];
    const float* bq = (const float*)d_in[3];
    const float* wk = (const float*)d_in[4];
    const float* bk = (const float*)d_in[5];
    const float* wv = (const float*)d_in[6];
    const float* bv = (const float*)d_in[7];
    const float* wo = (const float*)d_in[8];
    const float* bo = (const float*)d_in[9];
    float* out = (float*)d_out;

    float *Qp, *Kp, *Vp, *Op, *WTp;
    uint4 *Kfp, *Vfp;
    cudaGetSymbolAddress((void**)&Qp, g_Q);
    cudaGetSymbolAddress((void**)&Kp, g_K);
    cudaGetSymbolAddress((void**)&Vp, g_V);
    cudaGetSymbolAddress((void**)&Op, g_O);
    cudaGetSymbolAddress((void**)&WTp, g_WT);
    cudaGetSymbolAddress((void**)&Kfp, g_Kf);
    cudaGetSymbolAddress((void**)&Vfp, g_Vf);
    float* WTq = WTp + 0 * (size_t)D_MODEL * D_MODEL;
    float* WTk = WTp + 1 * (size_t)D_MODEL * D_MODEL;
    float* WTv = WTp + 2 * (size_t)D_MODEL * D_MODEL;
    float* WTo = WTp + 3 * (size_t)D_MODEL * D_MODEL;

    cudaFuncSetAttribute(attn_mma_kernel,
                         cudaFuncAttributeMaxDynamicSharedMemorySize,
                         ATTN_SMEM_BYTES);

    const dim3 tblk(32, 8);
    const dim3 tgrid(D_MODEL / 32, D_MODEL / 32);
    transpose_w<<<tgrid, tblk>>>(wq, WTq);
    transpose_w<<<tgrid, tblk>>>(wk, WTk);
    transpose_w<<<tgrid, tblk>>>(wv, WTv);
    transpose_w<<<tgrid, tblk>>>(wo, WTo);

    const dim3 ggrid(D_MODEL / 128, MTOT / 128);  // (8, 64)
    gemm_bf16_mma<<<ggrid, 256>>>(x, WTq, bq, Qp, MTOT, D_MODEL, D_MODEL);
    gemm_bf16_mma<<<ggrid, 256>>>(y, WTk, bk, Kp, MTOT, D_MODEL, D_MODEL);
    gemm_bf16_mma<<<ggrid, 256>>>(y, WTv, bv, Vp, MTOT, D_MODEL, D_MODEL);

    const dim3 fgrid(SEQ / 64, BATCH * NHEAD);    // (32, 64)
    build_kf<<<fgrid, 1024>>>(Kp, Kfp);
    build_vf<<<fgrid, 1024>>>(Vp, Vfp);

    const dim3 attn_grid(SEQ / 128, BATCH * NHEAD);  // (16, 64)
    attn_mma_kernel<<<attn_grid, 256, ATTN_SMEM_BYTES>>>(Qp, Kfp, Vfp, Op);

    gemm_bf16_mma<<<ggrid, 256>>>(Op, WTo, bo, out, MTOT, D_MODEL, D_MODEL);
}

// round 17
// speedup vs baseline: 1.7376x; 1.7376x over previous
#include <cuda_runtime.h>
#include <cstdint>
#include <cstddef>

#define D_MODEL 1024
#define NHEAD   16
#define HEAD_DIM 64
#define BATCH   4
#define SEQ     2048
#define MTOT    (BATCH * SEQ)   // 8192

// Scratch (device globals: allocation-free)
__device__ float g_Q[MTOT * D_MODEL];
__device__ float g_K[MTOT * D_MODEL];
__device__ float g_V[MTOT * D_MODEL];
__device__ float g_O[MTOT * D_MODEL];
__device__ float g_WT[4][D_MODEL * D_MODEL];     // transposed weights [N,K]
// Fragment-major split-bf16 K/V: [bh][kt][frag(32)][lane(32)] uint4
__device__ uint4 g_Kf[64 * 32 * 32 * 32];
__device__ uint4 g_Vf[64 * 32 * 32 * 32];

// ---------------------------------------------------------------------------
// bf16 + async helpers
// ---------------------------------------------------------------------------
__device__ __forceinline__ uint32_t pack_bf16x2(float y, float x) {
    uint32_t r;
    asm("cvt.rn.bf16x2.f32 %0, %1, %2;" : "=r"(r) : "f"(y), "f"(x));
    return r;
}

__device__ __forceinline__ void mma_bf16(float* d, const uint32_t* a,
                                         const uint32_t* b) {
    asm volatile(
        "mma.sync.aligned.m16n8k16.row.col.f32.bf16.bf16.f32 "
        "{%0,%1,%2,%3}, {%4,%5,%6,%7}, {%8,%9}, {%0,%1,%2,%3};\n"
        : "+f"(d[0]), "+f"(d[1]), "+f"(d[2]), "+f"(d[3])
        : "r"(a[0]), "r"(a[1]), "r"(a[2]), "r"(a[3]),
          "r"(b[0]), "r"(b[1]));
}

__device__ __forceinline__ void split4(float4 v, uint32_t& h01, uint32_t& l01,
                                       uint32_t& h23, uint32_t& l23) {
    h01 = pack_bf16x2(v.y, v.x);
    h23 = pack_bf16x2(v.w, v.z);
    const float hx = __uint_as_float(h01 << 16);
    const float hy = __uint_as_float(h01 & 0xFFFF0000u);
    const float hz = __uint_as_float(h23 << 16);
    const float hw = __uint_as_float(h23 & 0xFFFF0000u);
    l01 = pack_bf16x2(v.y - hy, v.x - hx);
    l23 = pack_bf16x2(v.w - hw, v.z - hz);
}

__device__ __forceinline__ void split2(float p0, float p1,
                                       uint32_t& hi, uint32_t& lo) {
    hi = pack_bf16x2(p1, p0);
    const float h0 = __uint_as_float(hi << 16);
    const float h1 = __uint_as_float(hi & 0xFFFF0000u);
    lo = pack_bf16x2(p1 - h1, p0 - h0);
}

__device__ __forceinline__ uint32_t smem_u32(const void* p) {
    uint32_t a;
    asm("{ .reg .u64 t; cvta.to.shared.u64 t, %1; cvt.u32.u64 %0, t; }"
        : "=r"(a) : "l"(p));
    return a;
}

__device__ __forceinline__ void cp_async16(uint32_t dst, const void* src) {
    asm volatile("cp.async.cg.shared.global [%0], [%1], 16;"
                 :: "r"(dst), "l"(src) : "memory");
}
#define CP_COMMIT() asm volatile("cp.async.commit_group;" ::: "memory")
#define CP_WAIT(n)  asm volatile("cp.async.wait_group %0;" :: "n"(n) : "memory")

// ---------------------------------------------------------------------------
// 1024x1024 transpose: WT[n,k] = W[k,n]
// ---------------------------------------------------------------------------
__global__ void __launch_bounds__(256) transpose_w(
    const float* __restrict__ W, float* __restrict__ WT)
{
    __shared__ float tile[32][33];
    const int bx = blockIdx.x * 32, by = blockIdx.y * 32;
    const int tx = threadIdx.x, ty = threadIdx.y;
    #pragma unroll
    for (int i = 0; i < 32; i += 8)
        tile[ty + i][tx] = W[(size_t)(by + ty + i) * D_MODEL + bx + tx];
    __syncthreads();
    #pragma unroll
    for (int i = 0; i < 32; i += 8)
        WT[(size_t)(bx + ty + i) * D_MODEL + by + tx] = tile[tx][ty + i];
}

// ---------------------------------------------------------------------------
// Pre-pass: build K fragments. Grid (32 kt, 64 bh), block 1024.
// ---------------------------------------------------------------------------
__global__ void __launch_bounds__(1024) build_kf(
    const float* __restrict__ gK, uint4* __restrict__ Kf)
{
    const int kt = blockIdx.x, bh = blockIdx.y;
    const int b = bh >> 4, h = bh & 15;
    const int fi = threadIdx.x >> 5;     // ks*8 + nt
    const int lane = threadIdx.x & 31;
    const int ks = fi >> 3, nt = fi & 7;
    const int r = lane >> 2, c = lane & 3;

    const float* row = gK + ((size_t)(b * SEQ + kt * 64 + nt * 8 + r)) * D_MODEL
                          + h * HEAD_DIM + 16 * ks;
    const float2 a = *(const float2*)(row + 2 * c);
    const float2 d = *(const float2*)(row + 2 * c + 8);
    uint32_t h0, l0, h1, l1;
    split2(a.x, a.y, h0, l0);
    split2(d.x, d.y, h1, l1);
    Kf[((size_t)(bh * 32 + kt) * 32 + fi) * 32 + lane] = make_uint4(h0, h1, l0, l1);
}

// ---------------------------------------------------------------------------
// Pre-pass: build V fragments (transposed).
// ---------------------------------------------------------------------------
__global__ void __launch_bounds__(1024) build_vf(
    const float* __restrict__ gV, uint4* __restrict__ Vf)
{
    const int kt = blockIdx.x, bh = blockIdx.y;
    const int b = bh >> 4, h = bh & 15;
    const int fi = threadIdx.x >> 5;     // pk*8 + nt
    const int lane = threadIdx.x & 31;
    const int pk = fi >> 3, nt = fi & 7;
    const int r = lane >> 2, c = lane & 3;
    const int d = nt * 8 + r;

    const int kA = kt * 64 + 2 * (8 * pk + c);
    const int kB = kt * 64 + 2 * (8 * pk + c + 4);
    const float* base = gV + (size_t)(b * SEQ) * D_MODEL + h * HEAD_DIM + d;
    const float vA0 = base[(size_t)kA * D_MODEL];
    const float vA1 = base[(size_t)(kA + 1) * D_MODEL];
    const float vB0 = base[(size_t)kB * D_MODEL];
    const float vB1 = base[(size_t)(kB + 1) * D_MODEL];
    uint32_t h0, l0, h1, l1;
    split2(vA0, vA1, h0, l0);
    split2(vB0, vB1, h1, l1);
    Vf[((size_t)(bh * 32 + kt) * 32 + fi) * 32 + lane] = make_uint4(h0, h1, l0, l1);
}

// ---------------------------------------------------------------------------
// Tensor-core GEMM, bf16 split mma + register-staged gmem prefetch.
// (Unchanged — measured at its mma floor, ~120us per GEMM.)
// ---------------------------------------------------------------------------
#define GW 36

__global__ void __launch_bounds__(256) gemm_bf16_mma(
    const float* __restrict__ A, const float* __restrict__ WT,
    const float* __restrict__ bias, float* __restrict__ C,
    int M, int N, int K)
{
    __shared__ uint32_t As[128][GW];
    __shared__ uint32_t Bs[128][GW];

    const int tid  = threadIdx.x;
    const int wid  = tid >> 5;
    const int lane = tid & 31;
    const int wm   = wid & 1;
    const int wn   = wid >> 1;
    const int bm   = blockIdx.y * 128;
    const int bn   = blockIdx.x * 128;

    const int r = lane >> 2;
    const int c = lane & 3;

    float acc[4][4][4];
    #pragma unroll
    for (int mt = 0; mt < 4; mt++)
        #pragma unroll
        for (int nt = 0; nt < 4; nt++)
            #pragma unroll
            for (int i = 0; i < 4; i++) acc[mt][nt][i] = 0.0f;

    const int lrow = tid >> 1;
    const int lcol = (tid & 1) * 16;
    const float* Arow = A  + (size_t)(bm + lrow) * K + lcol;
    const float* Brow = WT + (size_t)(bn + lrow) * K + lcol;

    float4 ra[4], rb[4];
    #pragma unroll
    for (int j = 0; j < 4; j++) {
        ra[j] = *(const float4*)(Arow + 4 * j);
        rb[j] = *(const float4*)(Brow + 4 * j);
    }

    for (int kt = 0; kt < K; kt += 32) {
        #pragma unroll
        for (int j = 0; j < 4; j++) {
            const int w = (lcol >> 1) + 2 * j;
            uint32_t h01, l01, h23, l23;
            split4(ra[j], h01, l01, h23, l23);
            *(uint2*)&As[lrow][w]      = make_uint2(h01, h23);
            *(uint2*)&As[lrow][16 + w] = make_uint2(l01, l23);
            split4(rb[j], h01, l01, h23, l23);
            *(uint2*)&Bs[lrow][w]      = make_uint2(h01, h23);
            *(uint2*)&Bs[lrow][16 + w] = make_uint2(l01, l23);
        }
        __syncthreads();

        if (kt + 32 < K) {
            #pragma unroll
            for (int j = 0; j < 4; j++) {
                ra[j] = *(const float4*)(Arow + kt + 32 + 4 * j);
                rb[j] = *(const float4*)(Brow + kt + 32 + 4 * j);
            }
        }

        #pragma unroll
        for (int ks = 0; ks < 2; ks++) {
            const int kw = ks * 8;

            uint32_t ahi[4][4], alo[4][4];
            #pragma unroll
            for (int mt = 0; mt < 4; mt++) {
                const int m0 = 64 * wm + 16 * mt;
                ahi[mt][0] = As[m0 + r][kw + c];
                ahi[mt][1] = As[m0 + r + 8][kw + c];
                ahi[mt][2] = As[m0 + r][kw + c + 4];
                ahi[mt][3] = As[m0 + r + 8][kw + c + 4];
                alo[mt][0] = As[m0 + r][16 + kw + c];
                alo[mt][1] = As[m0 + r + 8][16 + kw + c];
                alo[mt][2] = As[m0 + r][16 + kw + c + 4];
                alo[mt][3] = As[m0 + r + 8][16 + kw + c + 4];
            }

            uint32_t bhi[4][2], blo[4][2];
            #pragma unroll
            for (int nt = 0; nt < 4; nt++) {
                const int n0 = 32 * wn + 8 * nt;
                bhi[nt][0] = Bs[n0 + r][kw + c];
                bhi[nt][1] = Bs[n0 + r][kw + c + 4];
                blo[nt][0] = Bs[n0 + r][16 + kw + c];
                blo[nt][1] = Bs[n0 + r][16 + kw + c + 4];
            }

            #pragma unroll
            for (int mt = 0; mt < 4; mt++)
                #pragma unroll
                for (int nt = 0; nt < 4; nt++) {
                    mma_bf16(acc[mt][nt], ahi[mt], bhi[nt]);
                    mma_bf16(acc[mt][nt], ahi[mt], blo[nt]);
                    mma_bf16(acc[mt][nt], alo[mt], bhi[nt]);
                }
        }
        __syncthreads();
    }

    #pragma unroll
    for (int mt = 0; mt < 4; mt++) {
        const int row = bm + 64 * wm + 16 * mt + r;
        #pragma unroll
        for (int nt = 0; nt < 4; nt++) {
            const int col = bn + 32 * wn + 8 * nt + 2 * c;
            const float b0 = bias[col], b1 = bias[col + 1];
            float2 v0 = make_float2(acc[mt][nt][0] + b0, acc[mt][nt][1] + b1);
            float2 v1 = make_float2(acc[mt][nt][2] + b0, acc[mt][nt][3] + b1);
            *(float2*)(C + (size_t)row * N + col) = v0;
            *(float2*)(C + (size_t)(row + 8) * N + col) = v1;
        }
    }
}

// ---------------------------------------------------------------------------
// Tensor-core flash attention: pre-converted gmem fragments staged through
// double-buffered smem via cp.async (pure bulk copy, no conversion).
// 128 queries per block (8 warps). Grid (SEQ/128, B*H).
// Max-free softmax, deferred sum reduction.
// smem: Qs 128x68 words (34816B) + 2 buffers x (K 16KB + V 16KB) = 100352B.
// ---------------------------------------------------------------------------
#define AS_STRIDE 68
#define TILE_U4   2048   // uint4 per buffer: K frags [0,1024), V frags [1024,2048)
#define ATTN_SMEM_BYTES (128 * AS_STRIDE * 4 + 2 * TILE_U4 * 16)

__global__ void __launch_bounds__(256) attn_mma_kernel(
    const float* __restrict__ gQ, const uint4* __restrict__ Kf,
    const uint4* __restrict__ Vf, float* __restrict__ gO)
{
    extern __shared__ uint32_t smw[];
    uint32_t* Qs  = smw;                           // 128 x 68 words
    uint4*    buf = (uint4*)(smw + 128 * AS_STRIDE);   // 2 x 2048 uint4

    const int t    = threadIdx.x;
    const int wid  = t >> 5;
    const int lane = t & 31;
    const int r    = lane >> 2;
    const int c    = lane & 3;
    const int bh   = blockIdx.y;
    const int b    = bh >> 4;
    const int h    = bh & 15;
    const int qt   = blockIdx.x;

    const uint4* KfB = Kf + (size_t)bh * 32 * 1024;   // 1024 uint4 per tile
    const uint4* VfB = Vf + (size_t)bh * 32 * 1024;
    const uint32_t bufAddr = smem_u32(buf);

    // ---- Kick off tile 0 copy ----
    {
        const uint4* sK = KfB + t;
        const uint4* sV = VfB + t;
        #pragma unroll
        for (int i = 0; i < 4; i++) {
            cp_async16(bufAddr + (t + 256 * i) * 16, sK + 256 * i);
            cp_async16(bufAddr + (1024 + t + 256 * i) * 16, sV + 256 * i);
        }
        CP_COMMIT();
    }

    // ---- Fill Q (scaled by 1/8), split bf16: 128 rows ----
    {
        const int row   = t >> 1;
        const int dbase = (t & 1) * 32;
        const float* src = gQ + ((size_t)(b * SEQ + qt * 128 + row)) * D_MODEL
                               + h * HEAD_DIM + dbase;
        #pragma unroll
        for (int j = 0; j < 8; j++) {
            float4 v = *(const float4*)(src + 4 * j);
            v.x *= 0.125f; v.y *= 0.125f; v.z *= 0.125f; v.w *= 0.125f;
            uint32_t h01, l01, h23, l23;
            split4(v, h01, l01, h23, l23);
            const int w = (dbase >> 1) + 2 * j;
            Qs[row * AS_STRIDE + w]          = h01;
            Qs[row * AS_STRIDE + w + 1]      = h23;
            Qs[row * AS_STRIDE + 32 + w]     = l01;
            Qs[row * AS_STRIDE + 32 + w + 1] = l23;
        }
    }
    __syncthreads();

    // ---- Hoist Q fragments (per warp: rows 16*wid..+15) ----
    const int m0 = 16 * wid;
    uint32_t qhi[4][4], qlo[4][4];
    #pragma unroll
    for (int ks = 0; ks < 4; ks++) {
        const int kw = ks * 8;
        qhi[ks][0] = Qs[(m0 + r) * AS_STRIDE + kw + c];
        qhi[ks][1] = Qs[(m0 + r + 8) * AS_STRIDE + kw + c];
        qhi[ks][2] = Qs[(m0 + r) * AS_STRIDE + kw + c + 4];
        qhi[ks][3] = Qs[(m0 + r + 8) * AS_STRIDE + kw + c + 4];
        qlo[ks][0] = Qs[(m0 + r) * AS_STRIDE + 32 + kw + c];
        qlo[ks][1] = Qs[(m0 + r + 8) * AS_STRIDE + 32 + kw + c];
        qlo[ks][2] = Qs[(m0 + r) * AS_STRIDE + 32 + kw + c + 4];
        qlo[ks][3] = Qs[(m0 + r + 8) * AS_STRIDE + 32 + kw + c + 4];
    }

    float accO[8][4];
    #pragma unroll
    for (int nt = 0; nt < 8; nt++)
        #pragma unroll
        for (int i = 0; i < 4; i++) accO[nt][i] = 0.0f;
    float lr0 = 0.0f, lr1 = 0.0f;

    for (int kt = 0; kt < SEQ / 64; kt++) {
        // Prefetch tile kt+1 into the other buffer (its last readers finished
        // at the trailing __syncthreads of iteration kt-1).
        if (kt + 1 < SEQ / 64) {
            const uint32_t nb = bufAddr + ((kt + 1) & 1) * TILE_U4 * 16;
            const uint4* sK = KfB + (size_t)(kt + 1) * 1024 + t;
            const uint4* sV = VfB + (size_t)(kt + 1) * 1024 + t;
            #pragma unroll
            for (int i = 0; i < 4; i++) {
                cp_async16(nb + (t + 256 * i) * 16, sK + 256 * i);
                cp_async16(nb + (1024 + t + 256 * i) * 16, sV + 256 * i);
            }
            CP_COMMIT();
            CP_WAIT(1);
        } else {
            CP_WAIT(0);
        }
        __syncthreads();

        const uint4* kf = buf + (kt & 1) * TILE_U4 + lane;
        const uint4* vf = kf + 1024;

        // ---- Scores S = Q K^T (16 x 64 per warp) ----
        float acc[8][4];
        #pragma unroll
        for (int nt = 0; nt < 8; nt++)
            #pragma unroll
            for (int i = 0; i < 4; i++) acc[nt][i] = 0.0f;

        #pragma unroll
        for (int ks = 0; ks < 4; ks++) {
            #pragma unroll
            for (int nt = 0; nt < 8; nt++) {
                const uint4 kb = kf[(ks * 8 + nt) * 32];
                const uint32_t bhi[2] = {kb.x, kb.y};
                const uint32_t blo[2] = {kb.z, kb.w};
                mma_bf16(acc[nt], qhi[ks], bhi);
                mma_bf16(acc[nt], qhi[ks], blo);
                mma_bf16(acc[nt], qlo[ks], bhi);
            }
        }

        // ---- Max-free softmax: P = exp(S); accumulate local sums ----
        #pragma unroll
        for (int nt = 0; nt < 8; nt++) {
            acc[nt][0] = __expf(acc[nt][0]);
            acc[nt][1] = __expf(acc[nt][1]);
            acc[nt][2] = __expf(acc[nt][2]);
            acc[nt][3] = __expf(acc[nt][3]);
            lr0 += acc[nt][0] + acc[nt][1];
            lr1 += acc[nt][2] + acc[nt][3];
        }

        // ---- O += P V ----
        #pragma unroll
        for (int pk = 0; pk < 4; pk++) {
            uint32_t phi[4], plo[4];
            split2(acc[2 * pk][0],     acc[2 * pk][1],     phi[0], plo[0]);
            split2(acc[2 * pk][2],     acc[2 * pk][3],     phi[1], plo[1]);
            split2(acc[2 * pk + 1][0], acc[2 * pk + 1][1], phi[2], plo[2]);
            split2(acc[2 * pk + 1][2], acc[2 * pk + 1][3], phi[3], plo[3]);
            #pragma unroll
            for (int nt = 0; nt < 8; nt++) {
                const uint4 vb = vf[(pk * 8 + nt) * 32];
                const uint32_t vhi[2] = {vb.x, vb.y};
                const uint32_t vlo[2] = {vb.z, vb.w};
                mma_bf16(accO[nt], phi, vhi);
                mma_bf16(accO[nt], phi, vlo);
                mma_bf16(accO[nt], plo, vhi);
            }
        }
        __syncthreads();
    }

    // ---- Deferred sum reduction + epilogue ----
    lr0 += __shfl_xor_sync(0xffffffffu, lr0, 1);
    lr0 += __shfl_xor_sync(0xffffffffu, lr0, 2);
    lr1 += __shfl_xor_sync(0xffffffffu, lr1, 1);
    lr1 += __shfl_xor_sync(0xffffffffu, lr1, 2);
    const float rc0 = 1.0f / lr0;
    const float rc1 = 1.0f / lr1;
    const size_t row0 = (size_t)(b * SEQ + qt * 128 + m0 + r) * D_MODEL
                        + h * HEAD_DIM;
    const size_t row1 = row0 + 8 * D_MODEL;
    #pragma unroll
    for (int nt = 0; nt < 8; nt++) {
        const int col = 8 * nt + 2 * c;
        *(float2*)(gO + row0 + col) =
            make_float2(accO[nt][0] * rc0, accO[nt][1] * rc0);
        *(float2*)(gO + row1 + col) =
            make_float2(accO[nt][2] * rc1, accO[nt][3] * rc1);
    }
}

// ---------------------------------------------------------------------------
extern "C" void kernel_launch(void* const* d_in, const int* in_sizes, int n_in,
                              void* d_out, int out_size)
{
    const float* x  = (const float*)d_in[0];
    const float* y  = (const float*)d_in[1];
    const float* wq = (const float*)d_in[2];
    const float* bq = (const float*)d_in[3];
    const float* wk = (const float*)d_in[4];
    const float* bk = (const float*)d_in[5];
    const float* wv = (const float*)d_in[6];
    const float* bv = (const float*)d_in[7];
    const float* wo = (const float*)d_in[8];
    const float* bo = (const float*)d_in[9];
    float* out = (float*)d_out;

    float *Qp, *Kp, *Vp, *Op, *WTp;
    uint4 *Kfp, *Vfp;
    cudaGetSymbolAddress((void**)&Qp, g_Q);
    cudaGetSymbolAddress((void**)&Kp, g_K);
    cudaGetSymbolAddress((void**)&Vp, g_V);
    cudaGetSymbolAddress((void**)&Op, g_O);
    cudaGetSymbolAddress((void**)&WTp, g_WT);
    cudaGetSymbolAddress((void**)&Kfp, g_Kf);
    cudaGetSymbolAddress((void**)&Vfp, g_Vf);
    float* WTq = WTp + 0 * (size_t)D_MODEL * D_MODEL;
    float* WTk = WTp + 1 * (size_t)D_MODEL * D_MODEL;
    float* WTv = WTp + 2 * (size_t)D_MODEL * D_MODEL;
    float* WTo = WTp + 3 * (size_t)D_MODEL * D_MODEL;

    cudaFuncSetAttribute(attn_mma_kernel,
                         cudaFuncAttributeMaxDynamicSharedMemorySize,
                         ATTN_SMEM_BYTES);

    const dim3 tblk(32, 8);
    const dim3 tgrid(D_MODEL / 32, D_MODEL / 32);
    transpose_w<<<tgrid, tblk>>>(wq, WTq);
    transpose_w<<<tgrid, tblk>>>(wk, WTk);
    transpose_w<<<tgrid, tblk>>>(wv, WTv);
    transpose_w<<<tgrid, tblk>>>(wo, WTo);

    const dim3 ggrid(D_MODEL / 128, MTOT / 128);  // (8, 64)
    gemm_bf16_mma<<<ggrid, 256>>>(x, WTq, bq, Qp, MTOT, D_MODEL, D_MODEL);
    gemm_bf16_mma<<<ggrid, 256>>>(y, WTk, bk, Kp, MTOT, D_MODEL, D_MODEL);
    gemm_bf16_mma<<<ggrid, 256>>>(y, WTv, bv, Vp, MTOT, D_MODEL, D_MODEL);

    const dim3 fgrid(SEQ / 64, BATCH * NHEAD);    // (32, 64)
    build_kf<<<fgrid, 1024>>>(Kp, Kfp);
    build_vf<<<fgrid, 1024>>>(Vp, Vfp);

    const dim3 attn_grid(SEQ / 128, BATCH * NHEAD);  // (16, 64)
    attn_mma_kernel<<<attn_grid, 256, ATTN_SMEM_BYTES>>>(Qp, Kfp, Vfp, Op);

    gemm_bf16_mma<<<ggrid, 256>>>(Op, WTo, bo, out, MTOT, D_MODEL, D_MODEL);
}